// round 4
// baseline (speedup 1.0000x reference)
#include <cuda_runtime.h>
#include <cuda_bf16.h>

// PositionalEncoding: out[p][j] = X[p][j] + (j even ? sin(p*w_j) : cos(p*w_j))
//   w_j = 10000^{-(j + (j%2))/n},  n = 4096, m = 8192 rows.
//
// R4: 256-bit global accesses (ld/st.global.v8.f32, sm_100+) — each thread
// owns 8 consecutive columns. Exponents for cols 8u+{0..7} are
// (8u + {0,2,2,4,4,6,6,8})/n -> only 5 distinct frequencies -> 5 rotation
// states per thread. Angle-addition recurrence along rows as before.

#define PE_M     8192
#define PE_N     4096
#define PE_NV8   (PE_N / 8)      // 512 v8-groups per row
#define PE_ROWS  16              // rows per thread
#define PE_TPB   128

__device__ __forceinline__ void ldg_v8(const float* p, float* v) {
#if __CUDA_ARCH__ >= 1000
    asm volatile("ld.global.cs.v8.f32 {%0,%1,%2,%3,%4,%5,%6,%7}, [%8];"
                 : "=f"(v[0]), "=f"(v[1]), "=f"(v[2]), "=f"(v[3]),
                   "=f"(v[4]), "=f"(v[5]), "=f"(v[6]), "=f"(v[7])
                 : "l"(p));
#else
    float4 a = ((const float4*)p)[0], b = ((const float4*)p)[1];
    v[0]=a.x; v[1]=a.y; v[2]=a.z; v[3]=a.w;
    v[4]=b.x; v[5]=b.y; v[6]=b.z; v[7]=b.w;
#endif
}

__device__ __forceinline__ void stg_v8(float* p, const float* v) {
#if __CUDA_ARCH__ >= 1000
    asm volatile("st.global.cs.v8.f32 [%8], {%0,%1,%2,%3,%4,%5,%6,%7};"
                 :: "f"(v[0]), "f"(v[1]), "f"(v[2]), "f"(v[3]),
                    "f"(v[4]), "f"(v[5]), "f"(v[6]), "f"(v[7]),
                    "l"(p) : "memory");
#else
    ((float4*)p)[0] = make_float4(v[0], v[1], v[2], v[3]);
    ((float4*)p)[1] = make_float4(v[4], v[5], v[6], v[7]);
#endif
}

__global__ __launch_bounds__(PE_TPB, 12)
void pe_kernel(const float* __restrict__ X, float* __restrict__ Out) {
    const int u    = blockIdx.x * PE_TPB + threadIdx.x;  // v8-group index, 0..511
    const int row0 = blockIdx.y * PE_ROWS;

    const float L2_10K = 13.287712379549449f;  // log2(10000)

    // 5 distinct frequencies: exponents (8u + 2t)/n, t = 0..4
    float s[5], c[5], sw[5], cw[5];
#pragma unroll
    for (int t = 0; t < 5; t++) {
        const float e = (float)(8 * u + 2 * t) * (1.0f / (float)PE_N);
        const float w = exp2f(-e * L2_10K);           // 10000^{-e}
        sincosf((float)row0 * w, &s[t], &c[t]);       // precise: angle up to ~8191
        __sincosf(w, &sw[t], &cw[t]);                 // fast: w in (0, 1]
    }

    const float* __restrict__ xp = X   + (size_t)row0 * PE_N + 8 * (size_t)u;
    float*       __restrict__ yp = Out + (size_t)row0 * PE_N + 8 * (size_t)u;

#pragma unroll 4
    for (int r = 0; r < PE_ROWS; r++) {
        float v[8];
        ldg_v8(xp, v);
        // cols 8u+{0..7}: sin(w0), cos(w1), sin(w1), cos(w2), sin(w2), cos(w3), sin(w3), cos(w4)
        v[0] += s[0];
        v[1] += c[1];
        v[2] += s[1];
        v[3] += c[2];
        v[4] += s[2];
        v[5] += c[3];
        v[6] += s[3];
        v[7] += c[4];
        stg_v8(yp, v);
        xp += PE_N;
        yp += PE_N;
#pragma unroll
        for (int t = 0; t < 5; t++) {
            const float ns = fmaf(s[t], cw[t],  c[t] * sw[t]);
            const float nc = fmaf(c[t], cw[t], -s[t] * sw[t]);
            s[t] = ns; c[t] = nc;
        }
    }
}

extern "C" void kernel_launch(void* const* d_in, const int* in_sizes, int n_in,
                              void* d_out, int out_size) {
    (void)in_sizes; (void)n_in; (void)out_size;
    const float* X   = (const float*)d_in[0];
    float*       Out = (float*)d_out;

    dim3 block(PE_TPB);
    dim3 grid(PE_NV8 / PE_TPB, PE_M / PE_ROWS);   // (4, 512) = 2048 CTAs
    pe_kernel<<<grid, block>>>(X, Out);
}

// round 5
// speedup vs baseline: 1.0808x; 1.0808x over previous
#include <cuda_runtime.h>
#include <cuda_bf16.h>

// PositionalEncoding: out[p][j] = X[p][j] + (j even ? sin(p*w_j) : cos(p*w_j))
//   w_j = 10000^{-(j + (j%2))/n},  n = 4096, m = 8192 rows.
//
// R5: R3 structure (float4, TPB=128, ROWS=16, 4096 CTAs), shared-frequency
// recurrence (3 states/thread), but unroll 8 to front-batch 8 LDG.128 per
// thread and deepen per-warp MLP. Loads default policy, stores streaming.

#define PE_M     8192
#define PE_N     4096
#define PE_NV4   (PE_N / 4)      // 1024 float4 per row
#define PE_ROWS  16              // rows per thread
#define PE_TPB   128             // threads per block (column-quads)

__global__ __launch_bounds__(PE_TPB)
void pe_kernel(const float4* __restrict__ X, float4* __restrict__ Out) {
    const int cv   = blockIdx.x * PE_TPB + threadIdx.x;  // column-quad index, 0..1023
    const int row0 = blockIdx.y * PE_ROWS;

    const float L2_10K = 13.287712379549449f;  // log2(10000)

    // 3 distinct frequencies per quad: exponents (4cv + 2t)/n, t = 0,1,2
    float s[3], c[3], sw[3], cw[3];
#pragma unroll
    for (int t = 0; t < 3; t++) {
        const float e = (float)(4 * cv + 2 * t) * (1.0f / (float)PE_N);
        const float w = exp2f(-e * L2_10K);           // 10000^{-e}
        sincosf((float)row0 * w, &s[t], &c[t]);       // precise: angle up to ~8191
        __sincosf(w, &sw[t], &cw[t]);                 // fast: w in (0, 1]
    }

    const float4* __restrict__ xp = X   + (size_t)row0 * PE_NV4 + cv;
    float4*       __restrict__ yp = Out + (size_t)row0 * PE_NV4 + cv;

#pragma unroll 8
    for (int r = 0; r < PE_ROWS; r++) {
        float4 x = __ldg(xp);
        float4 y;
        // cols 4cv+{0,1,2,3}: sin(w0), cos(w1), sin(w1), cos(w2)
        y.x = x.x + s[0];
        y.y = x.y + c[1];
        y.z = x.z + s[1];
        y.w = x.w + c[2];
        __stcs(yp, y);
        xp += PE_NV4;
        yp += PE_NV4;
#pragma unroll
        for (int t = 0; t < 3; t++) {
            const float ns = fmaf(s[t], cw[t],  c[t] * sw[t]);
            const float nc = fmaf(c[t], cw[t], -s[t] * sw[t]);
            s[t] = ns; c[t] = nc;
        }
    }
}

extern "C" void kernel_launch(void* const* d_in, const int* in_sizes, int n_in,
                              void* d_out, int out_size) {
    (void)in_sizes; (void)n_in; (void)out_size;
    const float4* X   = (const float4*)d_in[0];
    float4*       Out = (float4*)d_out;

    dim3 block(PE_TPB);
    dim3 grid(PE_NV4 / PE_TPB, PE_M / PE_ROWS);   // (8, 512) = 4096 CTAs
    pe_kernel<<<grid, block>>>(X, Out);
}